// round 15
// baseline (speedup 1.0000x reference)
#include <cuda_runtime.h>
#include <cuda_fp16.h>
#include <stdint.h>
#include <math.h>

#define B_ 2
#define S_ 2048
#define E_ 1024
#define H_ 16
#define D_ 64
#define M_ (B_*S_)    // 4096
#define BH_ (B_*H_)   // 32

// ---------------- scratch (device globals; no allocation allowed) -------------
__device__ __half g_xh[(size_t)M_*E_];
__device__ __half g_wh[(size_t)4*E_*E_];
__device__ __half g_qh[(size_t)BH_*S_*D_];    // Q: fp16, pre-scaled by log2e/8
__device__ __half g_kh[(size_t)BH_*S_*D_];    // K: plain fp16
__device__ __half g_vth[(size_t)BH_*D_*S_];   // V^T: plain fp16 [bh][d][s]
__device__ __half g_oh[(size_t)M_*E_];        // attn out: plain fp16
__device__ unsigned int g_tile0;              // work-queue ctr: QKV gemm (768)
__device__ unsigned int g_tilef;              // work-queue ctr: flash (512)

// ---------------- helpers ----------------------------------------------------
__device__ __forceinline__ uint32_t smem_u32(const void* p) {
    uint32_t a;
    asm("{ .reg .u64 t; cvta.to.shared.u64 t, %1; cvt.u32.u64 %0, t; }" : "=r"(a) : "l"(p));
    return a;
}
__device__ __forceinline__ void cp16(uint32_t s, const void* g) {
    asm volatile("cp.async.cg.shared.global [%0], [%1], 16;" :: "r"(s), "l"(g));
}
#define CP_COMMIT() asm volatile("cp.async.commit_group;" ::: "memory")
#define CP_WAIT1()  asm volatile("cp.async.wait_group 1;" ::: "memory")

__device__ __forceinline__ void ldsm4(uint32_t addr, uint32_t r[4]) {
    asm volatile("ldmatrix.sync.aligned.m8n8.x4.shared.b16 {%0,%1,%2,%3}, [%4];"
        : "=r"(r[0]), "=r"(r[1]), "=r"(r[2]), "=r"(r[3]) : "r"(addr));
}
__device__ __forceinline__ void mma_fp16(float* c, const uint32_t* a, uint32_t b0, uint32_t b1) {
    asm volatile(
        "mma.sync.aligned.m16n8k16.row.col.f32.f16.f16.f32 "
        "{%0,%1,%2,%3}, {%4,%5,%6,%7}, {%8,%9}, {%0,%1,%2,%3};"
        : "+f"(c[0]), "+f"(c[1]), "+f"(c[2]), "+f"(c[3])
        : "r"(a[0]), "r"(a[1]), "r"(a[2]), "r"(a[3]), "r"(b0), "r"(b1));
}
__device__ __forceinline__ float fexp2(float x) {
    float r;
    asm("ex2.approx.f32 %0, %1;" : "=f"(r) : "f"(x));
    return r;
}
__device__ __forceinline__ uint32_t pack2(float x, float y) {
    __half2 h = __floats2half2_rn(x, y);
    return *(uint32_t*)&h;
}

// ---------------- fp32 -> fp16 conversion (+ work-queue reset) ----------------
__global__ __launch_bounds__(256) void convert_kernel(
    const float* __restrict__ x,  const float* __restrict__ Wq,
    const float* __restrict__ Wk, const float* __restrict__ Wv,
    const float* __restrict__ Wc)
{
    if (blockIdx.x == 0 && blockIdx.y == 0 && threadIdx.x == 0) {
        g_tile0 = 0u;    // reset persistent work queues every launch/replay
        g_tilef = 0u;
    }
    const int seg = blockIdx.y;
    const float* src; __half* hi; int n4;
    if (seg == 0) { src = x;  hi = g_xh; n4 = M_*E_/4; }
    else {
        src = (seg==1)?Wq:(seg==2)?Wk:(seg==3)?Wv:Wc;
        hi = g_wh + (size_t)(seg-1)*E_*E_;
        n4 = E_*E_/4;
    }
    int i = blockIdx.x * 256 + threadIdx.x;
    if (i >= n4) return;
    float4 v = ((const float4*)src)[i];
    ((__half2*)hi)[2*i]   = __floats2half2_rn(v.x, v.y);
    ((__half2*)hi)[2*i+1] = __floats2half2_rn(v.z, v.w);
}

// ---------------- HMMA GEMM (pure fp16, k-chunk 64) ---------------------------
// 128x128 tile, 8 warps (2x4), k-chunk 64, 3 stages (2 in flight), single
// barrier per chunk. MODE 0 is PERSISTENT: 304 CTAs pull 768 tiles off an
// atomic queue (deterministic: each tile's math is self-contained).
// MODE 1 (out = oh.Wh + bias) keeps classic grid (256 tiles < 296 slots).
#define GT_BYTES (128*128)        // 16384 (128B rows, XOR swizzle)
#define GSTAGE   (2*GT_BYTES)     // 32768
#define GSMEM    (3*GSTAGE)       // 98304 -> 2 CTAs/SM
#define NTILE0   768u

__device__ __forceinline__ uint32_t goff64(int r, int ch) {
    return (uint32_t)(r * 128 + ((ch ^ (r & 7)) << 4));
}

template<int MODE>
__global__ __launch_bounds__(256, 2) void gemm_kernel(float* __restrict__ out,
                                                      const float* __restrict__ bc)
{
    extern __shared__ char sm[];
    __shared__ unsigned int s_t;
    const uint32_t s0 = smem_u32(sm);
    const int tid = threadIdx.x;
    const int lane = tid & 31, warp = tid >> 5;
    const int wm = warp >> 2, wn = warp & 3;
    const int rowoff = (lane & 7) + ((lane >> 3) & 1) * 8;
    const int g = lane >> 2, tg2 = (lane & 3) * 2;

    for (;;) {
        int m0, n0, z = 0;
        if (MODE == 0) {
            if (tid == 0) s_t = atomicAdd(&g_tile0, 1u);
            __syncthreads();         // broadcast tile + prev-tile smem now free
            unsigned int t = s_t;
            if (t >= NTILE0) break;
            z = (int)(t >> 8);                   // 0..2
            int rem = (int)(t & 255u);
            m0 = (rem >> 3) * 128;               // 32 m-tiles
            n0 = (rem & 7) * 128;                // 8 n-tiles
        } else {
            m0 = blockIdx.y * 128;
            n0 = blockIdx.x * 128;
        }

        const __half* TA = (MODE == 0) ? g_xh : g_oh;
        const __half* TB = g_wh + (size_t)((MODE == 0) ? z : 3) * E_ * E_;

        float acc[4][4][4];
#pragma unroll
        for (int a = 0; a < 4; a++)
#pragma unroll
            for (int b = 0; b < 4; b++)
#pragma unroll
                for (int c = 0; c < 4; c++) acc[a][b][c] = 0.f;

        auto load = [&](int c) {
            const uint32_t base = s0 + (c % 3) * GSTAGE;
            const int k0 = c * 64;
#pragma unroll
            for (int i = 0; i < 8; i++) {
                int gg = i * 256 + tid;          // 0..2047
                int t2 = gg >> 10;               // 0..1 : A, B
                int r = (gg >> 3) & 127;
                int ch = gg & 7;
                const __half* src = t2 ? TB : TA;
                int row = (t2 ? n0 : m0) + r;
                cp16(base + t2 * GT_BYTES + goff64(r, ch),
                     src + (size_t)row * E_ + k0 + ch * 8);
            }
        };

        load(0); CP_COMMIT();
        load(1); CP_COMMIT();

        for (int c = 0; c < 16; c++) {
            CP_WAIT1();
            __syncthreads();
            if (c + 2 < 16) load(c + 2);
            CP_COMMIT();
            const uint32_t base = s0 + (c % 3) * GSTAGE;
#pragma unroll
            for (int i = 0; i < 4; i++) {
                const int ks = (i + warp) & 3;   // address-only rotation
                const int chunk = ks * 2 + (lane >> 4);
                uint32_t ah[4][4], bh[2][4];
#pragma unroll
                for (int mi = 0; mi < 4; mi++)
                    ldsm4(base + goff64(wm*64 + mi*16 + rowoff, chunk), ah[mi]);
#pragma unroll
                for (int p = 0; p < 2; p++)
                    ldsm4(base + GT_BYTES + goff64(wn*32 + p*16 + rowoff, chunk), bh[p]);
#pragma unroll
                for (int mi = 0; mi < 4; mi++) mma_fp16(acc[mi][0], ah[mi], bh[0][0], bh[0][2]);
#pragma unroll
                for (int mi = 0; mi < 4; mi++) mma_fp16(acc[mi][1], ah[mi], bh[0][1], bh[0][3]);
#pragma unroll
                for (int mi = 0; mi < 4; mi++) mma_fp16(acc[mi][2], ah[mi], bh[1][0], bh[1][2]);
#pragma unroll
                for (int mi = 0; mi < 4; mi++) mma_fp16(acc[mi][3], ah[mi], bh[1][1], bh[1][3]);
            }
        }

        if (MODE == 1) {
#pragma unroll
            for (int mi = 0; mi < 4; mi++) {
                int m = m0 + wm*64 + mi*16 + g;
#pragma unroll
                for (int ni = 0; ni < 4; ni++) {
                    int n = n0 + wn*32 + ni*8 + tg2;
                    float b0 = bc[n], b1 = bc[n+1];
                    *(float2*)(out + (size_t)m * E_ + n) =
                        make_float2(acc[mi][ni][0] + b0, acc[mi][ni][1] + b1);
                    *(float2*)(out + (size_t)(m+8) * E_ + n) =
                        make_float2(acc[mi][ni][2] + b0, acc[mi][ni][3] + b1);
                }
            }
            return;
        }

        // ---- MODE 0 epilogue: transpose via smem, per-row cumprod(cos) ----
        __syncthreads();
        float* st = (float*)sm;      // [128][132] fp32 = 67.6KB <= 96KB
#pragma unroll
        for (int mi = 0; mi < 4; mi++) {
            int r = wm*64 + mi*16 + g;
#pragma unroll
            for (int ni = 0; ni < 4; ni++) {
                int n = wn*32 + ni*8 + tg2;
                st[(size_t)r * 132 + n]     = acc[mi][ni][0];
                st[(size_t)r * 132 + n + 1] = acc[mi][ni][1];
                st[(size_t)(r+8) * 132 + n]     = acc[mi][ni][2];
                st[(size_t)(r+8) * 132 + n + 1] = acc[mi][ni][3];
            }
        }
        __syncthreads();

        {
            const int head = tid >> 7;          // 0..1
            const int r = tid & 127;
            const int m = m0 + r;
            const int b = m >> 11, sI = m & (S_ - 1);
            const int hglob = (n0 >> 6) + head;
            const int bh = b * H_ + hglob;
            const float* src = st + (size_t)r * 132 + head * 64;

            float run = 1.f;
            float val[64];
#pragma unroll
            for (int d = 0; d < 64; d++) { run *= __cosf(src[d]); val[d] = run; }

            if (z < 2) {
                const float sc = (z == 0) ? 0.18033688f : 1.0f;   // log2e/8
                __half hb[64];
#pragma unroll
                for (int d = 0; d < 64; d++) hb[d] = __float2half_rn(val[d] * sc);
                __half* dh = (z == 0 ? g_qh : g_kh) + ((size_t)bh * S_ + sI) * 64;
#pragma unroll
                for (int j = 0; j < 8; j++) ((uint4*)dh)[j] = ((uint4*)hb)[j];
            } else {
#pragma unroll
                for (int d = 0; d < 64; d++)
                    g_vth[((size_t)bh * 64 + d) * S_ + sI] = __float2half_rn(val[d]);
            }
        }
        // loop back: acquire-sync at top protects smem reuse
    }
}

// ---------------- HMMA flash attention (PERSISTENT) ---------------------------
// 304 CTAs pull 512 tiles (bh-major order -> consecutive tiles share K/V in
// L2). Plain fp16 Q/K/V, fp32 accum, no online max (|q.k| <= 64 bounded),
// 128-key super-tiles, 3-super ring.
#define FROWB 144
#define FKT  (64*FROWB)      // 9216
#define FSTAGE (2*FKT)       // 18432 : Kh, Vh (one 64-key sub-tile)
#define FSUPER (2*FSTAGE)    // 36864 (128-key super-tile)
#define FSMEM  (3*FSUPER)    // 110592 -> 2 CTAs/SM
#define NTILEF 512u

__global__ __launch_bounds__(256, 2) void flash_kernel()
{
    extern __shared__ char sm[];
    __shared__ unsigned int s_t;
    const uint32_t s0 = smem_u32(sm);
    const uint32_t sQ = s0 + 2 * FSUPER;   // Q parked in super 2 until ldsm
    const int tid = threadIdx.x, lane = tid & 31, warp = tid >> 5;
    const int rowoff = (lane & 7) + ((lane >> 3) & 1) * 8;

    for (;;) {
        if (tid == 0) s_t = atomicAdd(&g_tilef, 1u);
        __syncthreads();             // broadcast + prev-tile smem now free
        unsigned int t = s_t;
        if (t >= NTILEF) break;
        const int bh = (int)(t >> 4);            // consecutive tiles same head
        const int q0 = (int)(t & 15u) * 128;

        const __half* Qh = g_qh + (size_t)bh * S_ * 64;
        const __half* Kh = g_kh + (size_t)bh * S_ * 64;
        const __half* Vh = g_vth + (size_t)bh * 64 * S_;

        auto loadKV = [&](int tt) {   // tt = 64-key tile index (0..31)
            const uint32_t base = s0 + ((tt >> 1) % 3) * FSUPER + (tt & 1) * FSTAGE;
            const int kv0 = tt * 64;
#pragma unroll
            for (int i = 0; i < 4; i++) {
                int gi = i * 256 + tid;         // 0..1023
                int tl = gi >> 9;               // 0..1 : Kh, Vh
                int r = (gi >> 3) & 63;
                int ch = gi & 7;
                const __half* src = (tl == 0)
                    ? Kh + (size_t)(kv0 + r) * 64 + ch * 8
                    : Vh + (size_t)r * S_ + kv0 + ch * 8;
                cp16(base + tl * FKT + r * FROWB + ch * 16, src);
            }
        };

        {
            // group 0: Q (into super 2) + super 0; group 1: super 1
#pragma unroll
            for (int i = 0; i < 4; i++) {
                int gi = i * 256 + tid;
                int r = gi >> 3;
                int ch = gi & 7;
                cp16(sQ + r * FROWB + ch * 16, Qh + (size_t)(q0 + r) * 64 + ch * 8);
            }
            loadKV(0); loadKV(1); CP_COMMIT();
            loadKV(2); loadKV(3); CP_COMMIT();
        }

        float o[8][4];
#pragma unroll
        for (int i = 0; i < 8; i++)
#pragma unroll
            for (int j = 0; j < 4; j++) o[i][j] = 0.f;
        float l0r = 0.f, l1r = 0.f;
        uint32_t qhf[4][4];

        for (int u = 0; u < 16; u++) {           // 128-key super-tiles
            CP_WAIT1();
            __syncthreads();
            if (u == 0) {
                // one-time Q fragment load; CTA-wide before super-2 prefetch
#pragma unroll
                for (int ks = 0; ks < 4; ks++) {
                    uint32_t ra = sQ + (warp*16 + rowoff) * FROWB + (ks*2 + (lane>>4)) * 16;
                    ldsm4(ra, qhf[ks]);
                }
                __syncthreads();
            }
            if (u + 2 < 16) { loadKV(2*u + 4); loadKV(2*u + 5); }
            CP_COMMIT();

#pragma unroll
            for (int tt = 0; tt < 2; tt++) {     // two 64-key sub-tiles
                const uint32_t kb = s0 + (u % 3) * FSUPER + tt * FSTAGE;

                float s[8][4];
#pragma unroll
                for (int i = 0; i < 8; i++)
#pragma unroll
                    for (int j = 0; j < 4; j++) s[i][j] = 0.f;

                // S = Q K^T : per static ks, batch 4 K-panel ldsm4, 8 mma
#pragma unroll
                for (int ks = 0; ks < 4; ks++) {
                    const int chunk = ks * 2 + (lane >> 4);
                    uint32_t kh[4][4];
#pragma unroll
                    for (int q = 0; q < 4; q++)
                        ldsm4(kb + (q*16 + rowoff) * FROWB + chunk * 16, kh[q]);
#pragma unroll
                    for (int q = 0; q < 4; q++) mma_fp16(s[2*q],   qhf[ks], kh[q][0], kh[q][2]);
#pragma unroll
                    for (int q = 0; q < 4; q++) mma_fp16(s[2*q+1], qhf[ks], kh[q][1], kh[q][3]);
                }

                // p = 2^s (bounded; no max tracking), local l accumulate
                uint32_t pf[8][2];
#pragma unroll
                for (int ni = 0; ni < 8; ni++) {
                    float p0 = fexp2(s[ni][0]);
                    float p1 = fexp2(s[ni][1]);
                    float p2 = fexp2(s[ni][2]);
                    float p3 = fexp2(s[ni][3]);
                    l0r += p0 + p1; l1r += p2 + p3;
                    pf[ni][0] = pack2(p0, p1);
                    pf[ni][1] = pack2(p2, p3);
                }

                // O += P V : per static ks, batch 4 V-panel ldsm4, 8 mma
                const uint32_t vb = kb + FKT;
#pragma unroll
                for (int ks = 0; ks < 4; ks++) {
                    uint32_t a[4] = { pf[2*ks][0], pf[2*ks][1], pf[2*ks+1][0], pf[2*ks+1][1] };
                    const int chunk = ks * 2 + (lane >> 4);
                    uint32_t vh[4][4];
#pragma unroll
                    for (int q = 0; q < 4; q++)
                        ldsm4(vb + (q*16 + rowoff) * FROWB + chunk * 16, vh[q]);
#pragma unroll
                    for (int q = 0; q < 4; q++) mma_fp16(o[2*q],   a, vh[q][0], vh[q][2]);
#pragma unroll
                    for (int q = 0; q < 4; q++) mma_fp16(o[2*q+1], a, vh[q][1], vh[q][3]);
                }
            }
        }

        // epilogue: reduce l across the quad, normalize, write fp16 [B,S,H,D]
        l0r += __shfl_xor_sync(0xffffffffu, l0r, 1);
        l0r += __shfl_xor_sync(0xffffffffu, l0r, 2);
        l1r += __shfl_xor_sync(0xffffffffu, l1r, 1);
        l1r += __shfl_xor_sync(0xffffffffu, l1r, 2);
        const float inv0 = 1.f / l0r, inv1 = 1.f / l1r;
        const int g = lane >> 2, tg2 = (lane & 3) * 2;
        const int b = bh >> 4, h = bh & 15;
        const int sA = q0 + warp * 16 + g;
#pragma unroll
        for (int ni = 0; ni < 8; ni++) {
            int d = ni * 8 + tg2;
            size_t i0 = (((size_t)(b * S_ + sA)     * H_ + h) * D_ + d);
            size_t i1 = (((size_t)(b * S_ + sA + 8) * H_ + h) * D_ + d);
            *(__half2*)(g_oh + i0) = __floats2half2_rn(o[ni][0] * inv0, o[ni][1] * inv0);
            *(__half2*)(g_oh + i1) = __floats2half2_rn(o[ni][2] * inv1, o[ni][3] * inv1);
        }
        // loop back: acquire-sync at top protects smem reuse
    }
}

// ---------------------------------------------------------------------------
extern "C" void kernel_launch(void* const* d_in, const int* in_sizes, int n_in,
                              void* d_out, int out_size)
{
    const float* x  = (const float*)d_in[0];
    const float* Wq = (const float*)d_in[1];
    const float* Wk = (const float*)d_in[2];
    const float* Wv = (const float*)d_in[3];
    const float* Wc = (const float*)d_in[4];
    const float* bc = (const float*)d_in[5];
    float* out = (float*)d_out;

    cudaFuncSetAttribute(gemm_kernel<0>, cudaFuncAttributeMaxDynamicSharedMemorySize, GSMEM);
    cudaFuncSetAttribute(gemm_kernel<1>, cudaFuncAttributeMaxDynamicSharedMemorySize, GSMEM);
    cudaFuncSetAttribute(flash_kernel,   cudaFuncAttributeMaxDynamicSharedMemorySize, FSMEM);

    // 1) fp32 -> fp16 for x and all weights (+ resets the work queues)
    convert_kernel<<<dim3(4096, 5), 256>>>(x, Wq, Wk, Wv, Wc);

    // 2) QKV projections: persistent queue over 768 tiles
    gemm_kernel<0><<<304, 256, GSMEM>>>(nullptr, nullptr);

    // 3) flash attention: persistent queue over 512 tiles
    flash_kernel<<<304, 256, FSMEM>>>();

    // 4) output projection (single wave) + bias
    gemm_kernel<1><<<dim3(E_/128, M_/128, 1), 256, GSMEM>>>(out, bc);
}

// round 16
// speedup vs baseline: 1.1277x; 1.1277x over previous
#include <cuda_runtime.h>
#include <cuda_fp16.h>
#include <stdint.h>
#include <math.h>

#define B_ 2
#define S_ 2048
#define E_ 1024
#define H_ 16
#define D_ 64
#define M_ (B_*S_)    // 4096
#define BH_ (B_*H_)   // 32

// ---------------- scratch (device globals; no allocation allowed) -------------
__device__ __half g_xh[(size_t)M_*E_];
__device__ __half g_wh[(size_t)4*E_*E_];
__device__ __half g_qh[(size_t)BH_*S_*D_];    // Q: fp16, pre-scaled by log2e/8
__device__ __half g_kh[(size_t)BH_*S_*D_];    // K: plain fp16
__device__ __half g_vth[(size_t)BH_*D_*S_];   // V^T: plain fp16 [bh][d][s]
__device__ __half g_oh[(size_t)M_*E_];        // attn out: plain fp16

// ---------------- helpers ----------------------------------------------------
__device__ __forceinline__ uint32_t smem_u32(const void* p) {
    uint32_t a;
    asm("{ .reg .u64 t; cvta.to.shared.u64 t, %1; cvt.u32.u64 %0, t; }" : "=r"(a) : "l"(p));
    return a;
}
__device__ __forceinline__ void cp16(uint32_t s, const void* g) {
    asm volatile("cp.async.cg.shared.global [%0], [%1], 16;" :: "r"(s), "l"(g));
}
#define CP_COMMIT() asm volatile("cp.async.commit_group;" ::: "memory")
#define CP_WAIT1()  asm volatile("cp.async.wait_group 1;" ::: "memory")
#define CP_WAIT2()  asm volatile("cp.async.wait_group 2;" ::: "memory")

__device__ __forceinline__ void ldsm4(uint32_t addr, uint32_t r[4]) {
    asm volatile("ldmatrix.sync.aligned.m8n8.x4.shared.b16 {%0,%1,%2,%3}, [%4];"
        : "=r"(r[0]), "=r"(r[1]), "=r"(r[2]), "=r"(r[3]) : "r"(addr));
}
__device__ __forceinline__ void mma_fp16(float* c, const uint32_t* a, uint32_t b0, uint32_t b1) {
    asm volatile(
        "mma.sync.aligned.m16n8k16.row.col.f32.f16.f16.f32 "
        "{%0,%1,%2,%3}, {%4,%5,%6,%7}, {%8,%9}, {%0,%1,%2,%3};"
        : "+f"(c[0]), "+f"(c[1]), "+f"(c[2]), "+f"(c[3])
        : "r"(a[0]), "r"(a[1]), "r"(a[2]), "r"(a[3]), "r"(b0), "r"(b1));
}
__device__ __forceinline__ float fexp2(float x) {
    float r;
    asm("ex2.approx.f32 %0, %1;" : "=f"(r) : "f"(x));
    return r;
}
__device__ __forceinline__ uint32_t pack2(float x, float y) {
    __half2 h = __floats2half2_rn(x, y);
    return *(uint32_t*)&h;
}

// ---------------- fp32 -> fp16 conversion ------------------------------------
__global__ __launch_bounds__(256) void convert_kernel(
    const float* __restrict__ x,  const float* __restrict__ Wq,
    const float* __restrict__ Wk, const float* __restrict__ Wv,
    const float* __restrict__ Wc)
{
    const int seg = blockIdx.y;
    const float* src; __half* hi; int n4;
    if (seg == 0) { src = x;  hi = g_xh; n4 = M_*E_/4; }
    else {
        src = (seg==1)?Wq:(seg==2)?Wk:(seg==3)?Wv:Wc;
        hi = g_wh + (size_t)(seg-1)*E_*E_;
        n4 = E_*E_/4;
    }
    int i = blockIdx.x * 256 + threadIdx.x;
    if (i >= n4) return;
    float4 v = ((const float4*)src)[i];
    ((__half2*)hi)[2*i]   = __floats2half2_rn(v.x, v.y);
    ((__half2*)hi)[2*i+1] = __floats2half2_rn(v.z, v.w);
}

// ---------------- HMMA GEMM (pure fp16, k-chunk 64) ---------------------------
// Champion gemm (R14): 128x128 tile, 8 warps (2x4), k-chunk 64, 3 stages
// (2 in flight), single barrier per chunk, batched 6-ldsm per k-step,
// address-only warp rotation. Classic grid.
#define GT_BYTES (128*128)        // 16384 (128B rows, XOR swizzle)
#define GSTAGE   (2*GT_BYTES)     // 32768
#define GSMEM    (3*GSTAGE)       // 98304 -> 2 CTAs/SM

__device__ __forceinline__ uint32_t goff64(int r, int ch) {
    return (uint32_t)(r * 128 + ((ch ^ (r & 7)) << 4));
}

template<int MODE>
__global__ __launch_bounds__(256, 2) void gemm_kernel(float* __restrict__ out,
                                                      const float* __restrict__ bc)
{
    extern __shared__ char sm[];
    const uint32_t s0 = smem_u32(sm);
    const int tid = threadIdx.x;
    const int lane = tid & 31, warp = tid >> 5;
    const int wm = warp >> 2, wn = warp & 3;
    const int m0 = blockIdx.y * 128, n0 = blockIdx.x * 128;

    const __half* TA = (MODE == 0) ? g_xh : g_oh;
    const __half* TB = g_wh + (size_t)((MODE == 0) ? blockIdx.z : 3) * E_ * E_;

    float acc[4][4][4];
#pragma unroll
    for (int a = 0; a < 4; a++)
#pragma unroll
        for (int b = 0; b < 4; b++)
#pragma unroll
            for (int c = 0; c < 4; c++) acc[a][b][c] = 0.f;

    auto load = [&](int c) {
        const uint32_t base = s0 + (c % 3) * GSTAGE;
        const int k0 = c * 64;
#pragma unroll
        for (int i = 0; i < 8; i++) {
            int g = i * 256 + tid;           // 0..2047
            int t = g >> 10;                 // 0..1 : A, B
            int r = (g >> 3) & 127;
            int ch = g & 7;
            const __half* src = t ? TB : TA;
            int row = (t ? n0 : m0) + r;
            cp16(base + t * GT_BYTES + goff64(r, ch),
                 src + (size_t)row * E_ + k0 + ch * 8);
        }
    };

    load(0); CP_COMMIT();
    load(1); CP_COMMIT();

    const int rowoff = (lane & 7) + ((lane >> 3) & 1) * 8;

    for (int c = 0; c < 16; c++) {
        CP_WAIT1();              // group c complete (c+1 may pend)
        __syncthreads();         // copies visible + stage (c-1)%3 free
        if (c + 2 < 16) load(c + 2);   // -> stage (c+2)%3 == (c-1)%3 : safe
        CP_COMMIT();
        const uint32_t base = s0 + (c % 3) * GSTAGE;
#pragma unroll
        for (int i = 0; i < 4; i++) {
            const int ks = (i + warp) & 3;   // rotation feeds ADDRESSES only
            const int chunk = ks * 2 + (lane >> 4);
            uint32_t ah[4][4], bh[2][4];
            // batch ALL fragment loads first (ldsm MLP = 6)
#pragma unroll
            for (int mi = 0; mi < 4; mi++)
                ldsm4(base + goff64(wm*64 + mi*16 + rowoff, chunk), ah[mi]);
#pragma unroll
            for (int p = 0; p < 2; p++)
                ldsm4(base + GT_BYTES + goff64(wn*32 + p*16 + rowoff, chunk), bh[p]);
            // then the 16 mma, product-major
#pragma unroll
            for (int mi = 0; mi < 4; mi++) mma_fp16(acc[mi][0], ah[mi], bh[0][0], bh[0][2]);
#pragma unroll
            for (int mi = 0; mi < 4; mi++) mma_fp16(acc[mi][1], ah[mi], bh[0][1], bh[0][3]);
#pragma unroll
            for (int mi = 0; mi < 4; mi++) mma_fp16(acc[mi][2], ah[mi], bh[1][0], bh[1][2]);
#pragma unroll
            for (int mi = 0; mi < 4; mi++) mma_fp16(acc[mi][3], ah[mi], bh[1][1], bh[1][3]);
        }
    }

    const int g = lane >> 2, tg2 = (lane & 3) * 2;
    if (MODE == 1) {
#pragma unroll
        for (int mi = 0; mi < 4; mi++) {
            int m = m0 + wm*64 + mi*16 + g;
#pragma unroll
            for (int ni = 0; ni < 4; ni++) {
                int n = n0 + wn*32 + ni*8 + tg2;
                float b0 = bc[n], b1 = bc[n+1];
                *(float2*)(out + (size_t)m * E_ + n) =
                    make_float2(acc[mi][ni][0] + b0, acc[mi][ni][1] + b1);
                *(float2*)(out + (size_t)(m+8) * E_ + n) =
                    make_float2(acc[mi][ni][2] + b0, acc[mi][ni][3] + b1);
            }
        }
        return;
    }

    // ---- MODE 0: transpose via smem, then per-row cumprod(cos) ----
    __syncthreads();
    float* st = (float*)sm;      // [128][132] fp32 = 67.6KB <= 96KB
#pragma unroll
    for (int mi = 0; mi < 4; mi++) {
        int r = wm*64 + mi*16 + g;
#pragma unroll
        for (int ni = 0; ni < 4; ni++) {
            int n = wn*32 + ni*8 + tg2;
            st[(size_t)r * 132 + n]     = acc[mi][ni][0];
            st[(size_t)r * 132 + n + 1] = acc[mi][ni][1];
            st[(size_t)(r+8) * 132 + n]     = acc[mi][ni][2];
            st[(size_t)(r+8) * 132 + n + 1] = acc[mi][ni][3];
        }
    }
    __syncthreads();

    {
        const int head = tid >> 7;          // 0..1 (two heads per 128-col tile)
        const int r = tid & 127;
        const int m = m0 + r;
        const int b = m >> 11, sI = m & (S_ - 1);
        const int hglob = blockIdx.x * 2 + head;
        const int bh = b * H_ + hglob;
        const int z = blockIdx.z;
        const float* src = st + (size_t)r * 132 + head * 64;

        float run = 1.f;
        float val[64];
#pragma unroll
        for (int d = 0; d < 64; d++) { run *= __cosf(src[d]); val[d] = run; }

        if (z < 2) {
            // Q pre-scale folds softmax 1/sqrt(D) AND log2(e) for ex2-softmax
            const float sc = (z == 0) ? 0.18033688f : 1.0f;   // log2e/8
            __half hb[64];
#pragma unroll
            for (int d = 0; d < 64; d++) hb[d] = __float2half_rn(val[d] * sc);
            __half* dh = (z == 0 ? g_qh : g_kh) + ((size_t)bh * S_ + sI) * 64;
#pragma unroll
            for (int j = 0; j < 8; j++) ((uint4*)dh)[j] = ((uint4*)hb)[j];
        } else {
#pragma unroll
            for (int d = 0; d < 64; d++)
                g_vth[((size_t)bh * 64 + d) * S_ + sI] = __float2half_rn(val[d]);
        }
    }
}

// ---------------- HMMA flash attention ---------------------------------------
// Champion flash (R11 form): grid (S/128, BH), 256 threads, 2 CTAs/SM.
// Plain fp16 Q/K/V (fp32 accum). NO online max (scores provably bounded:
// |q.k| <= 64 -> ex2 arg <= 11.6, p <= 3020 fp16-safe, l <= 6.2e6 fp32-safe).
// 4 KV stages of 18.4KB, 3 in flight (wait_group 2), one barrier per 64-key
// tile. Q staged through stage 3 (dead after one-time ldsm at t==0).
#define FROWB 144
#define FKT  (64*FROWB)      // 9216
#define FSTAGE (2*FKT)       // 18432 : Kh, Vh
#define FSMEM (4*FSTAGE)     // 73728 -> 2 CTAs/SM

__global__ __launch_bounds__(256, 2) void flash_kernel()
{
    extern __shared__ char sm[];
    const uint32_t s0 = smem_u32(sm);
    const uint32_t sQ = s0 + 3 * FSTAGE;   // Q lives in stage 3 until t==0 ldsm
    const int tid = threadIdx.x, lane = tid & 31, warp = tid >> 5;
    const int bh = blockIdx.y;
    const int q0 = blockIdx.x * 128;

    const __half* Qh = g_qh + (size_t)bh * S_ * 64;
    const __half* Kh = g_kh + (size_t)bh * S_ * 64;
    const __half* Vh = g_vth + (size_t)bh * 64 * S_;

    auto loadKV = [&](int t) {
        const uint32_t base = s0 + (t & 3) * FSTAGE;
        const int kv0 = t * 64;
#pragma unroll
        for (int i = 0; i < 4; i++) {
            int gi = i * 256 + tid;         // 0..1023
            int tl = gi >> 9;               // 0..1 : Kh, Vh
            int r = (gi >> 3) & 63;
            int ch = gi & 7;
            const __half* src = (tl == 0)
                ? Kh + (size_t)(kv0 + r) * 64 + ch * 8
                : Vh + (size_t)r * S_ + kv0 + ch * 8;
            cp16(base + tl * FKT + r * FROWB + ch * 16, src);
        }
    };

    {
        // group 0: Q (into stage 3) + KV0; group 1: KV1; group 2: KV2
#pragma unroll
        for (int i = 0; i < 4; i++) {
            int gi = i * 256 + tid;         // 0..1023
            int r = gi >> 3;                // 0..127
            int ch = gi & 7;
            cp16(sQ + r * FROWB + ch * 16, Qh + (size_t)(q0 + r) * 64 + ch * 8);
        }
        loadKV(0); CP_COMMIT();
        loadKV(1); CP_COMMIT();
        loadKV(2); CP_COMMIT();
    }

    float o[8][4];
#pragma unroll
    for (int i = 0; i < 8; i++)
#pragma unroll
        for (int j = 0; j < 4; j++) o[i][j] = 0.f;
    float l0r = 0.f, l1r = 0.f;

    uint32_t qhf[4][4];
    const int rowoff = (lane & 7) + ((lane >> 3) & 1) * 8;

    for (int t = 0; t < 32; t++) {
        CP_WAIT2();              // groups <= t done (2 younger may pend)
        __syncthreads();
        if (t == 0) {
            // one-time Q fragment load from stage 3; must finish CTA-wide
            // before loadKV(3) overwrites it
#pragma unroll
            for (int ks = 0; ks < 4; ks++) {
                uint32_t ra = sQ + (warp*16 + rowoff) * FROWB + (ks*2 + (lane>>4)) * 16;
                ldsm4(ra, qhf[ks]);
            }
            __syncthreads();
        }
        if (t + 3 < 32) loadKV(t + 3);   // -> stage (t+3)&3 == (t-1)&3 : safe
        CP_COMMIT();

        const uint32_t kb = s0 + (t & 3) * FSTAGE;

        float s[8][4];
#pragma unroll
        for (int i = 0; i < 8; i++)
#pragma unroll
            for (int j = 0; j < 4; j++) s[i][j] = 0.f;

        // S = Q K^T (Q pre-scaled by log2e/8), interleaved over panel pairs
#pragma unroll
        for (int ks = 0; ks < 4; ks++) {
            const int chunk = ks * 2 + (lane >> 4);
#pragma unroll
            for (int pp = 0; pp < 2; pp++) {
                uint32_t kh[2][4];
#pragma unroll
                for (int q = 0; q < 2; q++)
                    ldsm4(kb + ((pp*2+q)*16 + rowoff) * FROWB + chunk * 16, kh[q]);
#pragma unroll
                for (int q = 0; q < 2; q++) mma_fp16(s[2*(pp*2+q)],   qhf[ks], kh[q][0], kh[q][2]);
#pragma unroll
                for (int q = 0; q < 2; q++) mma_fp16(s[2*(pp*2+q)+1], qhf[ks], kh[q][1], kh[q][3]);
            }
        }

        // softmax numerator: p = 2^s (bounded, no max tracking), local l accum
        uint32_t pf[8][2];
#pragma unroll
        for (int ni = 0; ni < 8; ni++) {
            float p0 = fexp2(s[ni][0]);
            float p1 = fexp2(s[ni][1]);
            float p2 = fexp2(s[ni][2]);
            float p3 = fexp2(s[ni][3]);
            l0r += p0 + p1; l1r += p2 + p3;
            pf[ni][0] = pack2(p0, p1);
            pf[ni][1] = pack2(p2, p3);
        }

        // O += P V (plain fp16 V), interleaved over panel pairs
        const uint32_t vb = kb + FKT;
#pragma unroll
        for (int ks = 0; ks < 4; ks++) {
            uint32_t a[4] = { pf[2*ks][0], pf[2*ks][1], pf[2*ks+1][0], pf[2*ks+1][1] };
            const int chunk = ks * 2 + (lane >> 4);
#pragma unroll
            for (int pp = 0; pp < 2; pp++) {
                uint32_t vh[2][4];
#pragma unroll
                for (int q = 0; q < 2; q++)
                    ldsm4(vb + ((pp*2+q)*16 + rowoff) * FROWB + chunk * 16, vh[q]);
#pragma unroll
                for (int q = 0; q < 2; q++) mma_fp16(o[2*(pp*2+q)],   a, vh[q][0], vh[q][2]);
#pragma unroll
                for (int q = 0; q < 2; q++) mma_fp16(o[2*(pp*2+q)+1], a, vh[q][1], vh[q][3]);
            }
        }
    }

    // epilogue: reduce l across the quad, normalize, write fp16 [B,S,H,D]
    l0r += __shfl_xor_sync(0xffffffffu, l0r, 1);
    l0r += __shfl_xor_sync(0xffffffffu, l0r, 2);
    l1r += __shfl_xor_sync(0xffffffffu, l1r, 1);
    l1r += __shfl_xor_sync(0xffffffffu, l1r, 2);
    const float inv0 = 1.f / l0r, inv1 = 1.f / l1r;
    const int g = lane >> 2, tg2 = (lane & 3) * 2;
    const int b = bh >> 4, h = bh & 15;
    const int sA = q0 + warp * 16 + g;
#pragma unroll
    for (int ni = 0; ni < 8; ni++) {
        int d = ni * 8 + tg2;
        size_t i0 = (((size_t)(b * S_ + sA)     * H_ + h) * D_ + d);
        size_t i1 = (((size_t)(b * S_ + sA + 8) * H_ + h) * D_ + d);
        *(__half2*)(g_oh + i0) = __floats2half2_rn(o[ni][0] * inv0, o[ni][1] * inv0);
        *(__half2*)(g_oh + i1) = __floats2half2_rn(o[ni][2] * inv1, o[ni][3] * inv1);
    }
}

// ---------------------------------------------------------------------------
extern "C" void kernel_launch(void* const* d_in, const int* in_sizes, int n_in,
                              void* d_out, int out_size)
{
    const float* x  = (const float*)d_in[0];
    const float* Wq = (const float*)d_in[1];
    const float* Wk = (const float*)d_in[2];
    const float* Wv = (const float*)d_in[3];
    const float* Wc = (const float*)d_in[4];
    const float* bc = (const float*)d_in[5];
    float* out = (float*)d_out;

    cudaFuncSetAttribute(gemm_kernel<0>, cudaFuncAttributeMaxDynamicSharedMemorySize, GSMEM);
    cudaFuncSetAttribute(gemm_kernel<1>, cudaFuncAttributeMaxDynamicSharedMemorySize, GSMEM);
    cudaFuncSetAttribute(flash_kernel,   cudaFuncAttributeMaxDynamicSharedMemorySize, FSMEM);

    // 1) fp32 -> fp16 for x and all weights
    convert_kernel<<<dim3(4096, 5), 256>>>(x, Wq, Wk, Wv, Wc);

    // 2) QKV projections (pure fp16 HMMA, k64) + quantum cumprod(cos) epilogue
    gemm_kernel<0><<<dim3(E_/128, M_/128, 3), 256, GSMEM>>>(nullptr, nullptr);

    // 3) flash attention (fp16 Q/K/V, ex2 softmax, 4-stage 64-key pipeline)
    flash_kernel<<<dim3(S_/128, BH_), 256, FSMEM>>>();

    // 4) output projection (pure fp16 HMMA, k64) + bias
    gemm_kernel<1><<<dim3(E_/128, M_/128, 1), 256, GSMEM>>>(out, bc);
}

// round 17
// speedup vs baseline: 1.1688x; 1.0364x over previous
#include <cuda_runtime.h>
#include <cuda_fp16.h>
#include <stdint.h>
#include <math.h>

#define B_ 2
#define S_ 2048
#define E_ 1024
#define H_ 16
#define D_ 64
#define M_ (B_*S_)    // 4096
#define BH_ (B_*H_)   // 32

// ---------------- scratch (device globals; no allocation allowed) -------------
__device__ __half g_xh[(size_t)M_*E_];
__device__ __half g_wh[(size_t)4*E_*E_];
__device__ __half g_qh[(size_t)BH_*S_*D_];    // Q: fp16, pre-scaled by log2e/8
__device__ __half g_kh[(size_t)BH_*S_*D_];    // K: plain fp16 [bh][s][d]
__device__ __half g_vh[(size_t)BH_*S_*D_];    // V: plain fp16 [bh][s][d]
__device__ __half g_oh[(size_t)M_*E_];        // attn out: plain fp16

// ---------------- helpers ----------------------------------------------------
__device__ __forceinline__ uint32_t smem_u32(const void* p) {
    uint32_t a;
    asm("{ .reg .u64 t; cvta.to.shared.u64 t, %1; cvt.u32.u64 %0, t; }" : "=r"(a) : "l"(p));
    return a;
}
__device__ __forceinline__ void cp16(uint32_t s, const void* g) {
    asm volatile("cp.async.cg.shared.global [%0], [%1], 16;" :: "r"(s), "l"(g));
}
#define CP_COMMIT() asm volatile("cp.async.commit_group;" ::: "memory")
#define CP_WAIT1()  asm volatile("cp.async.wait_group 1;" ::: "memory")
#define CP_WAIT2()  asm volatile("cp.async.wait_group 2;" ::: "memory")

__device__ __forceinline__ void ldsm4(uint32_t addr, uint32_t r[4]) {
    asm volatile("ldmatrix.sync.aligned.m8n8.x4.shared.b16 {%0,%1,%2,%3}, [%4];"
        : "=r"(r[0]), "=r"(r[1]), "=r"(r[2]), "=r"(r[3]) : "r"(addr));
}
__device__ __forceinline__ void ldsm4t(uint32_t addr, uint32_t r[4]) {
    asm volatile("ldmatrix.sync.aligned.m8n8.x4.trans.shared.b16 {%0,%1,%2,%3}, [%4];"
        : "=r"(r[0]), "=r"(r[1]), "=r"(r[2]), "=r"(r[3]) : "r"(addr));
}
__device__ __forceinline__ void mma_fp16(float* c, const uint32_t* a, uint32_t b0, uint32_t b1) {
    asm volatile(
        "mma.sync.aligned.m16n8k16.row.col.f32.f16.f16.f32 "
        "{%0,%1,%2,%3}, {%4,%5,%6,%7}, {%8,%9}, {%0,%1,%2,%3};"
        : "+f"(c[0]), "+f"(c[1]), "+f"(c[2]), "+f"(c[3])
        : "r"(a[0]), "r"(a[1]), "r"(a[2]), "r"(a[3]), "r"(b0), "r"(b1));
}
__device__ __forceinline__ float fexp2(float x) {
    float r;
    asm("ex2.approx.f32 %0, %1;" : "=f"(r) : "f"(x));
    return r;
}
__device__ __forceinline__ uint32_t pack2(float x, float y) {
    __half2 h = __floats2half2_rn(x, y);
    return *(uint32_t*)&h;
}

// ---------------- fp32 -> fp16 conversion (8 elems/thread) --------------------
__global__ __launch_bounds__(256) void convert_kernel(
    const float* __restrict__ x,  const float* __restrict__ Wq,
    const float* __restrict__ Wk, const float* __restrict__ Wv,
    const float* __restrict__ Wc)
{
    const int seg = blockIdx.y;
    const float* src; __half* hi; int n8;
    if (seg == 0) { src = x;  hi = g_xh; n8 = M_*E_/8; }
    else {
        src = (seg==1)?Wq:(seg==2)?Wk:(seg==3)?Wv:Wc;
        hi = g_wh + (size_t)(seg-1)*E_*E_;
        n8 = E_*E_/8;
    }
    int i = blockIdx.x * 256 + threadIdx.x;
    if (i >= n8) return;
    float4 a = ((const float4*)src)[2*i];
    float4 b = ((const float4*)src)[2*i+1];
    uint4 o;
    o.x = pack2(a.x, a.y);
    o.y = pack2(a.z, a.w);
    o.z = pack2(b.x, b.y);
    o.w = pack2(b.z, b.w);
    ((uint4*)hi)[i] = o;
}

// ---------------- HMMA GEMM (pure fp16, k-chunk 64) ---------------------------
// Champion gemm: 128x128 tile, 8 warps (2x4), k-chunk 64, 3 stages (2 in
// flight), single barrier per chunk, batched 6-ldsm per k-step, address-only
// warp rotation. Classic grid.
#define GT_BYTES (128*128)        // 16384 (128B rows, XOR swizzle)
#define GSTAGE   (2*GT_BYTES)     // 32768
#define GSMEM    (3*GSTAGE)       // 98304 -> 2 CTAs/SM

__device__ __forceinline__ uint32_t goff64(int r, int ch) {
    return (uint32_t)(r * 128 + ((ch ^ (r & 7)) << 4));
}

template<int MODE>
__global__ __launch_bounds__(256, 2) void gemm_kernel(float* __restrict__ out,
                                                      const float* __restrict__ bc)
{
    extern __shared__ char sm[];
    const uint32_t s0 = smem_u32(sm);
    const int tid = threadIdx.x;
    const int lane = tid & 31, warp = tid >> 5;
    const int wm = warp >> 2, wn = warp & 3;
    const int m0 = blockIdx.y * 128, n0 = blockIdx.x * 128;

    const __half* TA = (MODE == 0) ? g_xh : g_oh;
    const __half* TB = g_wh + (size_t)((MODE == 0) ? blockIdx.z : 3) * E_ * E_;

    float acc[4][4][4];
#pragma unroll
    for (int a = 0; a < 4; a++)
#pragma unroll
        for (int b = 0; b < 4; b++)
#pragma unroll
            for (int c = 0; c < 4; c++) acc[a][b][c] = 0.f;

    auto load = [&](int c) {
        const uint32_t base = s0 + (c % 3) * GSTAGE;
        const int k0 = c * 64;
#pragma unroll
        for (int i = 0; i < 8; i++) {
            int g = i * 256 + tid;           // 0..2047
            int t = g >> 10;                 // 0..1 : A, B
            int r = (g >> 3) & 127;
            int ch = g & 7;
            const __half* src = t ? TB : TA;
            int row = (t ? n0 : m0) + r;
            cp16(base + t * GT_BYTES + goff64(r, ch),
                 src + (size_t)row * E_ + k0 + ch * 8);
        }
    };

    load(0); CP_COMMIT();
    load(1); CP_COMMIT();

    const int rowoff = (lane & 7) + ((lane >> 3) & 1) * 8;

    for (int c = 0; c < 16; c++) {
        CP_WAIT1();              // group c complete (c+1 may pend)
        __syncthreads();         // copies visible + stage (c-1)%3 free
        if (c + 2 < 16) load(c + 2);   // -> stage (c+2)%3 == (c-1)%3 : safe
        CP_COMMIT();
        const uint32_t base = s0 + (c % 3) * GSTAGE;
#pragma unroll
        for (int i = 0; i < 4; i++) {
            const int ks = (i + warp) & 3;   // rotation feeds ADDRESSES only
            const int chunk = ks * 2 + (lane >> 4);
            uint32_t ah[4][4], bh[2][4];
            // batch ALL fragment loads first (ldsm MLP = 6)
#pragma unroll
            for (int mi = 0; mi < 4; mi++)
                ldsm4(base + goff64(wm*64 + mi*16 + rowoff, chunk), ah[mi]);
#pragma unroll
            for (int p = 0; p < 2; p++)
                ldsm4(base + GT_BYTES + goff64(wn*32 + p*16 + rowoff, chunk), bh[p]);
            // then the 16 mma, product-major
#pragma unroll
            for (int mi = 0; mi < 4; mi++) mma_fp16(acc[mi][0], ah[mi], bh[0][0], bh[0][2]);
#pragma unroll
            for (int mi = 0; mi < 4; mi++) mma_fp16(acc[mi][1], ah[mi], bh[0][1], bh[0][3]);
#pragma unroll
            for (int mi = 0; mi < 4; mi++) mma_fp16(acc[mi][2], ah[mi], bh[1][0], bh[1][2]);
#pragma unroll
            for (int mi = 0; mi < 4; mi++) mma_fp16(acc[mi][3], ah[mi], bh[1][1], bh[1][3]);
        }
    }

    const int g = lane >> 2, tg2 = (lane & 3) * 2;
    if (MODE == 1) {
#pragma unroll
        for (int mi = 0; mi < 4; mi++) {
            int m = m0 + wm*64 + mi*16 + g;
#pragma unroll
            for (int ni = 0; ni < 4; ni++) {
                int n = n0 + wn*32 + ni*8 + tg2;
                float b0 = bc[n], b1 = bc[n+1];
                *(float2*)(out + (size_t)m * E_ + n) =
                    make_float2(acc[mi][ni][0] + b0, acc[mi][ni][1] + b1);
                *(float2*)(out + (size_t)(m+8) * E_ + n) =
                    make_float2(acc[mi][ni][2] + b0, acc[mi][ni][3] + b1);
            }
        }
        return;
    }

    // ---- MODE 0: transpose via smem, then per-row cumprod(cos) ----
    __syncthreads();
    float* st = (float*)sm;      // [128][132] fp32 = 67.6KB <= 96KB
#pragma unroll
    for (int mi = 0; mi < 4; mi++) {
        int r = wm*64 + mi*16 + g;
#pragma unroll
        for (int ni = 0; ni < 4; ni++) {
            int n = wn*32 + ni*8 + tg2;
            st[(size_t)r * 132 + n]     = acc[mi][ni][0];
            st[(size_t)r * 132 + n + 1] = acc[mi][ni][1];
            st[(size_t)(r+8) * 132 + n]     = acc[mi][ni][2];
            st[(size_t)(r+8) * 132 + n + 1] = acc[mi][ni][3];
        }
    }
    __syncthreads();

    {
        const int head = tid >> 7;          // 0..1 (two heads per 128-col tile)
        const int r = tid & 127;
        const int m = m0 + r;
        const int b = m >> 11, sI = m & (S_ - 1);
        const int hglob = blockIdx.x * 2 + head;
        const int bh = b * H_ + hglob;
        const int z = blockIdx.z;
        const float* src = st + (size_t)r * 132 + head * 64;

        float run = 1.f;
        float val[64];
#pragma unroll
        for (int d = 0; d < 64; d++) { run *= __cosf(src[d]); val[d] = run; }

        // unified vectorized row store: q (scaled log2e/8), k, v all [bh][s][d]
        const float sc = (z == 0) ? 0.18033688f : 1.0f;
        __half hb[64];
#pragma unroll
        for (int d = 0; d < 64; d++) hb[d] = __float2half_rn(val[d] * sc);
        __half* dh = (z == 0 ? g_qh : (z == 1 ? g_kh : g_vh)) + ((size_t)bh * S_ + sI) * 64;
#pragma unroll
        for (int j = 0; j < 8; j++) ((uint4*)dh)[j] = ((uint4*)hb)[j];
    }
}

// ---------------- HMMA flash attention ---------------------------------------
// Champion flash: grid (S/128, BH), 256 threads, 2 CTAs/SM. Plain fp16 Q/K/V
// (fp32 accum). NO online max (scores provably bounded: |q.k| <= 64 -> ex2
// arg <= 11.6, p <= 3020 fp16-safe, l <= 6.2e6 fp32-safe). 4 KV stages,
// 3 in flight (wait_group 2), one barrier per 64-key tile. V is stored
// [s][d] like K; PV B-frags come from ldmatrix.x4.TRANS (pairs r0/r1, r2/r3).
#define FROWB 144
#define FKT  (64*FROWB)      // 9216
#define FSTAGE (2*FKT)       // 18432 : K, V (one 64-key tile)
#define FSMEM (4*FSTAGE)     // 73728 -> 2 CTAs/SM

__global__ __launch_bounds__(256, 2) void flash_kernel()
{
    extern __shared__ char sm[];
    const uint32_t s0 = smem_u32(sm);
    const uint32_t sQ = s0 + 3 * FSTAGE;   // Q lives in stage 3 until t==0 ldsm
    const int tid = threadIdx.x, lane = tid & 31, warp = tid >> 5;
    const int bh = blockIdx.y;
    const int q0 = blockIdx.x * 128;

    const __half* Qh = g_qh + (size_t)bh * S_ * 64;
    const __half* Kh = g_kh + (size_t)bh * S_ * 64;
    const __half* Vh = g_vh + (size_t)bh * S_ * 64;

    auto loadKV = [&](int t) {
        const uint32_t base = s0 + (t & 3) * FSTAGE;
        const int kv0 = t * 64;
#pragma unroll
        for (int i = 0; i < 4; i++) {
            int gi = i * 256 + tid;         // 0..1023
            int tl = gi >> 9;               // 0..1 : K, V
            int r = (gi >> 3) & 63;
            int ch = gi & 7;
            const __half* src = ((tl == 0) ? Kh : Vh) + (size_t)(kv0 + r) * 64 + ch * 8;
            cp16(base + tl * FKT + r * FROWB + ch * 16, src);
        }
    };

    {
        // group 0: Q (into stage 3) + KV0; group 1: KV1; group 2: KV2
#pragma unroll
        for (int i = 0; i < 4; i++) {
            int gi = i * 256 + tid;         // 0..1023
            int r = gi >> 3;                // 0..127
            int ch = gi & 7;
            cp16(sQ + r * FROWB + ch * 16, Qh + (size_t)(q0 + r) * 64 + ch * 8);
        }
        loadKV(0); CP_COMMIT();
        loadKV(1); CP_COMMIT();
        loadKV(2); CP_COMMIT();
    }

    float o[8][4];
#pragma unroll
    for (int i = 0; i < 8; i++)
#pragma unroll
        for (int j = 0; j < 4; j++) o[i][j] = 0.f;
    float l0r = 0.f, l1r = 0.f;

    uint32_t qhf[4][4];
    const int rowoff = (lane & 7) + ((lane >> 3) & 1) * 8;

    for (int t = 0; t < 32; t++) {
        CP_WAIT2();              // groups <= t done (2 younger may pend)
        __syncthreads();
        if (t == 0) {
            // one-time Q fragment load from stage 3; must finish CTA-wide
            // before loadKV(3) overwrites it
#pragma unroll
            for (int ks = 0; ks < 4; ks++) {
                uint32_t ra = sQ + (warp*16 + rowoff) * FROWB + (ks*2 + (lane>>4)) * 16;
                ldsm4(ra, qhf[ks]);
            }
            __syncthreads();
        }
        if (t + 3 < 32) loadKV(t + 3);   // -> stage (t+3)&3 == (t-1)&3 : safe
        CP_COMMIT();

        const uint32_t kb = s0 + (t & 3) * FSTAGE;

        float s[8][4];
#pragma unroll
        for (int i = 0; i < 8; i++)
#pragma unroll
            for (int j = 0; j < 4; j++) s[i][j] = 0.f;

        // S = Q K^T (Q pre-scaled by log2e/8), interleaved over panel pairs
#pragma unroll
        for (int ks = 0; ks < 4; ks++) {
            const int chunk = ks * 2 + (lane >> 4);
#pragma unroll
            for (int pp = 0; pp < 2; pp++) {
                uint32_t kh[2][4];
#pragma unroll
                for (int q = 0; q < 2; q++)
                    ldsm4(kb + ((pp*2+q)*16 + rowoff) * FROWB + chunk * 16, kh[q]);
#pragma unroll
                for (int q = 0; q < 2; q++) mma_fp16(s[2*(pp*2+q)],   qhf[ks], kh[q][0], kh[q][2]);
#pragma unroll
                for (int q = 0; q < 2; q++) mma_fp16(s[2*(pp*2+q)+1], qhf[ks], kh[q][1], kh[q][3]);
            }
        }

        // softmax numerator: p = 2^s (bounded, no max tracking), local l accum
        uint32_t pf[8][2];
#pragma unroll
        for (int ni = 0; ni < 8; ni++) {
            float p0 = fexp2(s[ni][0]);
            float p1 = fexp2(s[ni][1]);
            float p2 = fexp2(s[ni][2]);
            float p3 = fexp2(s[ni][3]);
            l0r += p0 + p1; l1r += p2 + p3;
            pf[ni][0] = pack2(p0, p1);
            pf[ni][1] = pack2(p2, p3);
        }

        // O += P V : V tile is [keys][d]; B-frags via ldsm.x4.trans.
        // rows = keys (k-dim, 16 per ks), chunk = d-octet; per ldsm:
        // (r0,r1) = b-pair for d-octet 2*pair, (r2,r3) for 2*pair+1.
        const uint32_t vb = kb + FKT;
#pragma unroll
        for (int ks = 0; ks < 4; ks++) {
            uint32_t a[4] = { pf[2*ks][0], pf[2*ks][1], pf[2*ks+1][0], pf[2*ks+1][1] };
#pragma unroll
            for (int pair = 0; pair < 4; pair++) {
                const int chunk = pair * 2 + (lane >> 4);
                uint32_t vh[4];
                ldsm4t(vb + (ks*16 + rowoff) * FROWB + chunk * 16, vh);
                mma_fp16(o[2*pair],   a, vh[0], vh[1]);
                mma_fp16(o[2*pair+1], a, vh[2], vh[3]);
            }
        }
    }

    // epilogue: reduce l across the quad, normalize, write fp16 [B,S,H,D]
    l0r += __shfl_xor_sync(0xffffffffu, l0r, 1);
    l0r += __shfl_xor_sync(0xffffffffu, l0r, 2);
    l1r += __shfl_xor_sync(0xffffffffu, l1r, 1);
    l1r += __shfl_xor_sync(0xffffffffu, l1r, 2);
    const float inv0 = 1.f / l0r, inv1 = 1.f / l1r;
    const int g = lane >> 2, tg2 = (lane & 3) * 2;
    const int b = bh >> 4, h = bh & 15;
    const int sA = q0 + warp * 16 + g;
#pragma unroll
    for (int ni = 0; ni < 8; ni++) {
        int d = ni * 8 + tg2;
        size_t i0 = (((size_t)(b * S_ + sA)     * H_ + h) * D_ + d);
        size_t i1 = (((size_t)(b * S_ + sA + 8) * H_ + h) * D_ + d);
        *(__half2*)(g_oh + i0) = __floats2half2_rn(o[ni][0] * inv0, o[ni][1] * inv0);
        *(__half2*)(g_oh + i1) = __floats2half2_rn(o[ni][2] * inv1, o[ni][3] * inv1);
    }
}

// ---------------------------------------------------------------------------
extern "C" void kernel_launch(void* const* d_in, const int* in_sizes, int n_in,
                              void* d_out, int out_size)
{
    const float* x  = (const float*)d_in[0];
    const float* Wq = (const float*)d_in[1];
    const float* Wk = (const float*)d_in[2];
    const float* Wv = (const float*)d_in[3];
    const float* Wc = (const float*)d_in[4];
    const float* bc = (const float*)d_in[5];
    float* out = (float*)d_out;

    cudaFuncSetAttribute(gemm_kernel<0>, cudaFuncAttributeMaxDynamicSharedMemorySize, GSMEM);
    cudaFuncSetAttribute(gemm_kernel<1>, cudaFuncAttributeMaxDynamicSharedMemorySize, GSMEM);
    cudaFuncSetAttribute(flash_kernel,   cudaFuncAttributeMaxDynamicSharedMemorySize, FSMEM);

    // 1) fp32 -> fp16 for x and all weights (8 elems/thread)
    convert_kernel<<<dim3(2048, 5), 256>>>(x, Wq, Wk, Wv, Wc);

    // 2) QKV projections (pure fp16 HMMA, k64) + quantum cumprod(cos) epilogue
    gemm_kernel<0><<<dim3(E_/128, M_/128, 3), 256, GSMEM>>>(nullptr, nullptr);

    // 3) flash attention (fp16 Q/K/V, ex2 softmax, ldsm.trans V)
    flash_kernel<<<dim3(S_/128, BH_), 256, FSMEM>>>();

    // 4) output projection (pure fp16 HMMA, k64) + bias
    gemm_kernel<1><<<dim3(E_/128, M_/128, 1), 256, GSMEM>>>(out, bc);
}